// round 2
// baseline (speedup 1.0000x reference)
#include <cuda_runtime.h>
#include <math.h>

#define N_ROWS  8192
#define N_PROP  2000
#define THREADS 256
#define GROUPS  (N_PROP / 4)   // 500 groups of 4 proposals

// d_in[0]=rois (N,4), d_in[1]=rpn_rois (N,NP,5), d_in[2]=scores (N,NP,2)
// d_out = [sel_rpn_rois (N,4) | sel_scores (N,1)]

struct RefStats { float x, y, s, r_max, window; };

// Per-proposal math — bit-identical to the reference fp32 op order.
__device__ __forceinline__ float prop_score(const RefStats& R,
                                            float a0, float a1, float a2, float a3,
                                            float sc)
{
    const float PI_F = 3.14159274101257324219f;
    const float x_ = __fmul_rn(__fadd_rn(a0, a2), 0.5f);
    const float y_ = __fmul_rn(__fadd_rn(a1, a3), 0.5f);
    const float w_ = __fadd_rn(fabsf(__fadd_rn(a0, -a2)), 1e-4f);
    const float h_ = __fadd_rn(fabsf(__fadd_rn(a1, -a3)), 1e-4f);
    const float p_ = __fmul_rn(__fadd_rn(w_, h_), 0.5f);
    const float s_ = sqrtf(__fmul_rn(__fadd_rn(w_, p_), __fadd_rn(h_, p_)));

    const float smax = fmaxf(__fdiv_rn(R.s, s_), __fdiv_rn(s_, R.s));
    const float pen  = expf(__fmul_rn(-0.055f,
                          __fadd_rn(__fmul_rn(smax, R.r_max), -1.0f)));

    const float dx   = __fadd_rn(R.x, -x_);
    const float dy   = __fadd_rn(R.y, -y_);
    const float dist = sqrtf(__fadd_rn(__fmul_rn(dx, dx), __fmul_rn(dy, dy)));
    float han = __fadd_rn(0.5f, __fmul_rn(0.5f,
                    cosf(__fdiv_rn(__fmul_rn(dist, PI_F), R.window))));
    han = (dist > R.window) ? 0.0f : han;

    return __fadd_rn(__fmul_rn(sc, pen), __fmul_rn(han, 0.42f));
}

__global__ __launch_bounds__(THREADS)
void trnms_kernel(const float* __restrict__ rois,
                  const float* __restrict__ rpn,
                  const float* __restrict__ scores,
                  float* __restrict__ out)
{
    const int row = blockIdx.x;
    const int tid = threadIdx.x;

    RefStats R;
    {
        const float4 rr = *reinterpret_cast<const float4*>(rois + (size_t)row * 4);
        R.x = __fmul_rn(__fadd_rn(rr.x, rr.z), 0.5f);
        R.y = __fmul_rn(__fadd_rn(rr.y, rr.w), 0.5f);
        const float w = __fadd_rn(fabsf(__fadd_rn(rr.x, -rr.z)), 1e-4f);
        const float h = __fadd_rn(fabsf(__fadd_rn(rr.y, -rr.w)), 1e-4f);
        const float p = __fmul_rn(__fadd_rn(w, h), 0.5f);
        R.s = sqrtf(__fmul_rn(__fadd_rn(w, p), __fadd_rn(h, p)));
        const float ratio = __fdiv_rn(w, h);
        R.r_max  = fmaxf(ratio, __fdiv_rn(1.0f, ratio));
        R.window = __fmul_rn(R.s, 2.0f);
    }

    const float4* rb = reinterpret_cast<const float4*>(rpn    + (long long)row * (N_PROP * 5));
    const float4* sb = reinterpret_cast<const float4*>(scores + (long long)row * (N_PROP * 2));

    float best = -INFINITY;
    int   bidx = 0x7fffffff;

    // Each group g covers proposals 4g..4g+3:
    //   rpn float4s  [5g, 5g+5), scores float4s [2g, 2g+2)
    for (int g = tid; g < GROUPS; g += THREADS) {
        const float4 v0 = __ldg(rb + 5 * g + 0);
        const float4 v1 = __ldg(rb + 5 * g + 1);
        const float4 v2 = __ldg(rb + 5 * g + 2);
        const float4 v3 = __ldg(rb + 5 * g + 3);
        const float4 v4 = __ldg(rb + 5 * g + 4);
        const float4 sA = __ldg(sb + 2 * g + 0);
        const float4 sB = __ldg(sb + 2 * g + 1);

        const int j0 = 4 * g;

        float pw;
        pw = prop_score(R, v0.y, v0.z, v0.w, v1.x, sA.y);   // prop 4g+0
        if (pw > best) { best = pw; bidx = j0 + 0; }
        pw = prop_score(R, v1.z, v1.w, v2.x, v2.y, sA.w);   // prop 4g+1
        if (pw > best) { best = pw; bidx = j0 + 1; }
        pw = prop_score(R, v2.w, v3.x, v3.y, v3.z, sB.y);   // prop 4g+2
        if (pw > best) { best = pw; bidx = j0 + 2; }
        pw = prop_score(R, v4.x, v4.y, v4.z, v4.w, sB.w);   // prop 4g+3
        if (pw > best) { best = pw; bidx = j0 + 3; }
    }

    // ---- block argmax reduction, first-index wins on ties ----
    const int lane = tid & 31;
    const int wid  = tid >> 5;

    #pragma unroll
    for (int off = 16; off > 0; off >>= 1) {
        const float ov = __shfl_down_sync(0xffffffffu, best, off);
        const int   oi = __shfl_down_sync(0xffffffffu, bidx, off);
        if (ov > best || (ov == best && oi < bidx)) { best = ov; bidx = oi; }
    }

    __shared__ float sv[THREADS / 32];
    __shared__ int   si[THREADS / 32];
    if (lane == 0) { sv[wid] = best; si[wid] = bidx; }
    __syncthreads();

    if (wid == 0) {
        best = (lane < THREADS / 32) ? sv[lane] : -INFINITY;
        bidx = (lane < THREADS / 32) ? si[lane] : 0x7fffffff;
        #pragma unroll
        for (int off = (THREADS / 32) / 2; off > 0; off >>= 1) {
            const float ov = __shfl_down_sync(0xffffffffu, best, off);
            const int   oi = __shfl_down_sync(0xffffffffu, bidx, off);
            if (ov > best || (ov == best && oi < bidx)) { best = ov; bidx = oi; }
        }
        if (lane == 0) {
            const float* q = rpn + (long long)row * (N_PROP * 5) + (long long)bidx * 5;
            float* o = out + (size_t)row * 4;
            o[0] = q[1];
            o[1] = q[2];
            o[2] = q[3];
            o[3] = q[4];
            out[(size_t)N_ROWS * 4 + row] =
                scores[(long long)row * (N_PROP * 2) + bidx * 2 + 1];
        }
    }
}

extern "C" void kernel_launch(void* const* d_in, const int* in_sizes, int n_in,
                              void* d_out, int out_size)
{
    const float* rois   = (const float*)d_in[0];
    const float* rpn    = (const float*)d_in[1];
    const float* scores = (const float*)d_in[2];
    float* out = (float*)d_out;

    trnms_kernel<<<N_ROWS, THREADS>>>(rois, rpn, scores, out);
}